// round 16
// baseline (speedup 1.0000x reference)
#include <cuda_runtime.h>
#include <cuda_bf16.h>
#include <cstdint>
#include <cstddef>

#define TT 512
#define NBATCH 256
#define EE 256
#define HH 256
#define GG 1024
#define NBLK 128
#define CSIZE 8          // cluster size = CTAs per row-group

typedef unsigned long long ull;
union F2U { ull u; float2 f; };

// ---- packed f32x2 helpers ----
__device__ __forceinline__ ull bcast2(float x) {
    ull r; asm("mov.b64 %0, {%1, %1};" : "=l"(r) : "f"(x)); return r;
}
__device__ __forceinline__ ull pack2(float lo, float hi) {
    ull r; asm("mov.b64 %0, {%1, %2};" : "=l"(r) : "f"(lo), "f"(hi)); return r;
}
__device__ __forceinline__ void ffma2(ull& d, ull a, ull b) {
    asm("fma.rn.f32x2 %0, %1, %2, %0;" : "+l"(d) : "l"(a), "l"(b));
}

// ---- warp-MMA helpers (baseline sm_100: ldmatrix + mma.sync) ----
__device__ __forceinline__ uint32_t smem_u32(const void* p) {
    uint32_t a;
    asm("{ .reg .u64 t; cvta.to.shared.u64 t, %1; cvt.u32.u64 %0, t; }" : "=r"(a) : "l"(p));
    return a;
}
__device__ __forceinline__ void ldsm_x4(uint32_t* r, uint32_t addr) {
    asm volatile("ldmatrix.sync.aligned.m8n8.x4.shared.b16 {%0,%1,%2,%3}, [%4];"
                 : "=r"(r[0]), "=r"(r[1]), "=r"(r[2]), "=r"(r[3]) : "r"(addr));
}
__device__ __forceinline__ void ldsm_x2(uint32_t* r, uint32_t addr) {
    asm volatile("ldmatrix.sync.aligned.m8n8.x2.shared.b16 {%0,%1}, [%2];"
                 : "=r"(r[0]), "=r"(r[1]) : "r"(addr));
}
__device__ __forceinline__ void mma16816(float* d, const uint32_t* a, const uint32_t* b) {
    asm volatile(
        "mma.sync.aligned.m16n8k16.row.col.f32.bf16.bf16.f32 "
        "{%0,%1,%2,%3}, {%4,%5,%6,%7}, {%8,%9}, {%0,%1,%2,%3};"
        : "+f"(d[0]), "+f"(d[1]), "+f"(d[2]), "+f"(d[3])
        : "r"(a[0]), "r"(a[1]), "r"(a[2]), "r"(a[3]), "r"(b[0]), "r"(b[1]));
}
__device__ __forceinline__ uint32_t sw128(uint32_t bo) { return bo ^ ((bo >> 3) & 0x70); }

// ---------------- device scratch (g_xg fully rewritten each run: replay-safe) ----------------
__device__ __align__(16) float g_xg[(size_t)TT * NBATCH * GG];

__device__ __forceinline__ void split_store(char* hi_p, char* lo_p, float4 v) {
    __nv_bfloat16 hx = __float2bfloat16(v.x), hy = __float2bfloat16(v.y),
                  hz = __float2bfloat16(v.z), hw = __float2bfloat16(v.w);
    __nv_bfloat16 lx = __float2bfloat16(v.x - __bfloat162float(hx));
    __nv_bfloat16 ly = __float2bfloat16(v.y - __bfloat162float(hy));
    __nv_bfloat16 lz = __float2bfloat16(v.z - __bfloat162float(hz));
    __nv_bfloat16 lw = __float2bfloat16(v.w - __bfloat162float(hw));
    union { __nv_bfloat162 b[2]; uint2 u; } H, L;
    H.b[0] = __halves2bfloat162(hx, hy); H.b[1] = __halves2bfloat162(hz, hw);
    L.b[0] = __halves2bfloat162(lx, ly); L.b[1] = __halves2bfloat162(lz, lw);
    *(uint2*)hi_p = H.u;
    *(uint2*)lo_p = L.u;
}

// ---------------- phase 1: xg = x @ Wih^T + biases (split-bf16 mma.sync) ----------------
// (validated R14 design, reset branches removed)
__global__ void __launch_bounds__(256, 1) xg_gemm_kernel(
    const float* __restrict__ attn,   // (N, T, E)
    const float* __restrict__ Wih,    // (4H, E)
    const float* __restrict__ bih,
    const float* __restrict__ bhh) {
    extern __shared__ char dsm[];
    __shared__ float sbias[1024];

    const int mt = blockIdx.x;                 // 0..1023
    const int t  = mt >> 1;
    const int n0 = (mt & 1) << 7;
    const int tid = threadIdx.x;
    const int wid = tid >> 5, lane = tid & 31;

    const uint32_t dsm_u = smem_u32(dsm);
    const uint32_t base_u = (dsm_u + 1023u) & ~1023u;
    char* p = dsm + (base_u - dsm_u);
    char* aHi = p;
    char* aLo = p + 65536;
    char* bBuf = p + 131072;
    const uint32_t uaHi = base_u, uaLo = base_u + 65536, ubBuf = base_u + 131072;

    for (int i = tid; i < 1024; i += 256) sbias[i] = bih[i] + bhh[i];

    {
        const int arow = tid >> 4;
        const int acol = tid & 15;
#pragma unroll 1
        for (int round = 0; round < 8; round++) {
            int row = (round << 4) + arow;
            const float4* src = (const float4*)(attn + ((size_t)(n0 + row) * TT + t) * EE);
#pragma unroll
            for (int q = 0; q < 4; q++) {
                int c4 = acol + (q << 4);
                float4 v = src[c4];
                int kch = c4 >> 4;
                uint32_t so = sw128((row << 7) + ((c4 & 15) << 3));
                split_store(aHi + kch * 16384 + so, aLo + kch * 16384 + so, v);
            }
        }
    }

    const int brow_l = tid >> 4;
    const int bcol_l = tid & 15;

    float4 vb[8];
    {
        const float* wbase = Wih;
#pragma unroll
        for (int r = 0; r < 8; r++) {
            int row = (r << 4) + brow_l;
            vb[r] = *(const float4*)(wbase + (size_t)row * EE + (bcol_l << 2));
        }
#pragma unroll
        for (int r = 0; r < 8; r++) {
            int row = (r << 4) + brow_l;
            uint32_t so = sw128((row << 7) + (bcol_l << 3));
            split_store(bBuf + so, bBuf + 16384 + so, vb[r]);
        }
    }
    __syncthreads();

    const int m_base = (wid & 1) << 6;
    const int nb     = (wid >> 1) << 5;
    const int a_r = lane & 15;
    const int a_c = (lane >> 4) << 3;
    const int b_r = lane & 7;
    const int b_c = ((lane >> 3) & 1) << 3;
    const int gID = lane >> 2, t4 = lane & 3;

    int buf = 0;

#pragma unroll 1
    for (int gt = 0; gt < 8; gt++) {
        float d[4][4][4];
#pragma unroll
        for (int mi = 0; mi < 4; mi++)
#pragma unroll
            for (int ni = 0; ni < 4; ni++)
#pragma unroll
                for (int q = 0; q < 4; q++) d[mi][ni][q] = 0.f;

#pragma unroll 1
        for (int kch = 0; kch < 4; kch++) {
            const bool have_next = !(gt == 7 && kch == 3);
            if (have_next) {
                const int ngt = gt + (kch == 3 ? 1 : 0);
                const int nkch = (kch + 1) & 3;
                const float* wbase = Wih + (size_t)(ngt << 7) * EE + (nkch << 6);
#pragma unroll
                for (int r = 0; r < 8; r++) {
                    int row = (r << 4) + brow_l;
                    vb[r] = *(const float4*)(wbase + (size_t)row * EE + (bcol_l << 2));
                }
            }

            const uint32_t aH = uaHi + kch * 16384;
            const uint32_t aL = uaLo + kch * 16384;
            const uint32_t bH = ubBuf + buf * 32768;
            const uint32_t bL = bH + 16384;
#pragma unroll
            for (int combo = 0; combo < 3; combo++) {
                const uint32_t aBase = (combo == 2) ? aL : aH;
                const uint32_t bBase = (combo == 1) ? bL : bH;
#pragma unroll
                for (int k16 = 0; k16 < 4; k16++) {
                    const int kc = k16 << 4;
                    uint32_t afr[4][4];
#pragma unroll
                    for (int mi = 0; mi < 4; mi++) {
                        uint32_t bo = ((m_base + (mi << 4) + a_r) << 7) + ((kc + a_c) << 1);
                        ldsm_x4(afr[mi], aBase + sw128(bo));
                    }
                    uint32_t bfr[4][2];
#pragma unroll
                    for (int ni = 0; ni < 4; ni++) {
                        uint32_t bo = ((nb + (ni << 3) + b_r) << 7) + ((kc + b_c) << 1);
                        ldsm_x2(bfr[ni], bBase + sw128(bo));
                    }
#pragma unroll
                    for (int mi = 0; mi < 4; mi++)
#pragma unroll
                        for (int ni = 0; ni < 4; ni++)
                            mma16816(d[mi][ni], afr[mi], bfr[ni]);
                }
            }

            if (have_next) {
                char* nh = bBuf + (buf ^ 1) * 32768;
                char* nl = nh + 16384;
#pragma unroll
                for (int r = 0; r < 8; r++) {
                    int row = (r << 4) + brow_l;
                    uint32_t so = sw128((row << 7) + (bcol_l << 3));
                    split_store(nh + so, nl + so, vb[r]);
                }
            }
            __syncthreads();
            buf ^= 1;
        }

        const int g0 = gt << 7;
#pragma unroll
        for (int mi = 0; mi < 4; mi++) {
            const int row0 = m_base + (mi << 4) + gID;
#pragma unroll
            for (int ni = 0; ni < 4; ni++) {
                const int col = nb + (ni << 3) + (t4 << 1);
                const float bx = sbias[g0 + col], by = sbias[g0 + col + 1];
                size_t base0 = ((size_t)t * NBATCH + (n0 + row0)) * GG + g0 + col;
                size_t base1 = base0 + (size_t)8 * GG;
                *(float2*)&g_xg[base0] = make_float2(d[mi][ni][0] + bx, d[mi][ni][1] + by);
                *(float2*)&g_xg[base1] = make_float2(d[mi][ni][2] + bx, d[mi][ni][3] + by);
            }
        }
    }
}

#define XG_SMEM_BYTES (196608 + 1024)

// ---------------- phase 2: cluster-based persistent recurrent kernel ----------------
__device__ __forceinline__ float sigf(float x) { return 1.0f / (1.0f + __expf(-x)); }
__device__ __forceinline__ float tanh_fast(float x) { return 1.0f - 2.0f / (__expf(2.0f * x) + 1.0f); }

// 16 clusters of 8 CTAs (cluster = one row-group of 16 batch rows).
// Per step: read h from LOCAL hs2[cur] -> FFMA2 partials (packed Whh in regs) ->
// smem reduce -> gates -> DSMEM-broadcast h(t+1) into all 8 CTAs' hs2[nxt] ->
// hardware cluster barrier. No global h buffer, no software spin, no replay state.
__global__ void __launch_bounds__(256, 1) __cluster_dims__(CSIZE, 1, 1)
lstm_rec_kernel(
    const float* __restrict__ Whh,       // (4H, H)
    const int*   __restrict__ traj_len,  // (N,)
    float*       __restrict__ out) {     // (N, 1, H)
    extern __shared__ float red[];       // 64 KB dynamic
    __shared__ float hs2[2][16 * 256];   // 32 KB double-buffered h tile
    __shared__ int slen[16];

    const int tid = threadIdx.x;
    const int bn = blockIdx.x >> 3;      // row group 0..15
    uint32_t bj;                          // rank within cluster = gate slice
    asm("mov.u32 %0, %%cluster_ctarank;" : "=r"(bj));
    const int r0 = bn << 4;
    const int c0 = (int)bj << 5;
    const int ks = tid >> 5, gcg = tid & 31;

    // pack W_hh slice into f32x2 gate-pair registers
    ull pwA[32], pwB[32];
    {
        const float* wr[4];
#pragma unroll
        for (int q = 0; q < 4; q++) {
            int l = (gcg << 2) + q;
            int gr = ((l >> 5) << 8) + c0 + (l & 31);
            wr[q] = &Whh[(size_t)gr * HH + (ks << 5)];
        }
#pragma unroll
        for (int kc = 0; kc < 8; kc++) {
            float4 w0 = *(const float4*)(wr[0] + (kc << 2));
            float4 w1 = *(const float4*)(wr[1] + (kc << 2));
            float4 w2 = *(const float4*)(wr[2] + (kc << 2));
            float4 w3 = *(const float4*)(wr[3] + (kc << 2));
            pwA[(kc << 2) + 0] = pack2(w0.x, w1.x);
            pwA[(kc << 2) + 1] = pack2(w0.y, w1.y);
            pwA[(kc << 2) + 2] = pack2(w0.z, w1.z);
            pwA[(kc << 2) + 3] = pack2(w0.w, w1.w);
            pwB[(kc << 2) + 0] = pack2(w2.x, w3.x);
            pwB[(kc << 2) + 1] = pack2(w2.y, w3.y);
            pwB[(kc << 2) + 2] = pack2(w2.z, w3.z);
            pwB[(kc << 2) + 3] = pack2(w2.w, w3.w);
        }
    }

    // zero local hs2[0]; load lens
    for (int i = tid; i < 4096; i += 256) hs2[0][i] = 0.f;
    if (tid < 16) slen[tid] = traj_len[r0 + tid];

    const int er = tid >> 4, ep = tid & 15;
    const int n_e = r0 + er;
    const int len_e = traj_len[n_e];
    const int col_e = c0 + (ep << 1);
    float cc0 = 0.f, cc1 = 0.f, hk0 = 0.f, hk1 = 0.f;

    // precompute DSMEM addresses of this thread's h cell in all 8 CTAs, both buffers
    uint32_t rem0[CSIZE], rem1[CSIZE];
    {
        const uint32_t loc0 = smem_u32(&hs2[0][(er << 8) + col_e]);
        const uint32_t loc1 = smem_u32(&hs2[1][(er << 8) + col_e]);
#pragma unroll
        for (int rk = 0; rk < CSIZE; rk++) {
            asm("mapa.shared::cluster.u32 %0, %1, %2;" : "=r"(rem0[rk]) : "r"(loc0), "r"(rk));
            asm("mapa.shared::cluster.u32 %0, %1, %2;" : "=r"(rem1[rk]) : "r"(loc1), "r"(rk));
        }
    }
    __syncthreads();

    int gmax = 0;
#pragma unroll
    for (int r = 0; r < 16; r++) gmax = max(gmax, slen[r]);

    // prologue prefetch xg(0)
    float2 xi, xf, xg2, xo;
    if (0 < len_e) {
        const float* xgp = &g_xg[((size_t)n_e) * GG + col_e];
        xi  = __ldcs((const float2*)&xgp[0]);
        xf  = __ldcs((const float2*)&xgp[256]);
        xg2 = __ldcs((const float2*)&xgp[512]);
        xo  = __ldcs((const float2*)&xgp[768]);
    }

    int cur = 0;
    for (int t = 0; t < gmax; t++) {
        const bool valid = (t < len_e);
        const float* hb = hs2[cur];

        // GEMM partials over this warp's K-slice — skip frozen rows (uniform branch)
#pragma unroll 2
        for (int r = 0; r < 16; r++) {
            if (t < slen[r]) {
                const float4* hp = (const float4*)&hb[(r << 8) + (ks << 5)];
                ull accA = 0ull, accB = 0ull;
#pragma unroll
                for (int kc = 0; kc < 8; kc++) {
                    float4 hv = hp[kc];
                    ull h0 = bcast2(hv.x), h1 = bcast2(hv.y), h2 = bcast2(hv.z), h3 = bcast2(hv.w);
                    ffma2(accA, h0, pwA[(kc << 2) + 0]); ffma2(accB, h0, pwB[(kc << 2) + 0]);
                    ffma2(accA, h1, pwA[(kc << 2) + 1]); ffma2(accB, h1, pwB[(kc << 2) + 1]);
                    ffma2(accA, h2, pwA[(kc << 2) + 2]); ffma2(accB, h2, pwB[(kc << 2) + 2]);
                    ffma2(accA, h3, pwA[(kc << 2) + 3]); ffma2(accB, h3, pwB[(kc << 2) + 3]);
                }
                ulonglong2 st; st.x = accA; st.y = accB;
                *(ulonglong2*)&red[(((ks << 4) + r) << 7) + (gcg << 2)] = st;
            }
        }
        __syncthreads();

        if (valid) {
            float2 s[4];
#pragma unroll
            for (int typ = 0; typ < 4; typ++) {
                float sx = 0.f, sy = 0.f;
#pragma unroll
                for (int k2 = 0; k2 < 8; k2++) {
                    float2 v = *(const float2*)&red[(k2 << 11) + (er << 7) + (typ << 5) + (ep << 1)];
                    sx += v.x; sy += v.y;
                }
                s[typ] = make_float2(sx, sy);
            }
            {
                float gi = s[0].x + xi.x, gf = s[1].x + xf.x, gg = s[2].x + xg2.x, go = s[3].x + xo.x;
                float cn = sigf(gf) * cc0 + sigf(gi) * tanh_fast(gg);
                cc0 = cn; hk0 = sigf(go) * tanh_fast(cn);
            }
            {
                float gi = s[0].y + xi.y, gf = s[1].y + xf.y, gg = s[2].y + xg2.y, go = s[3].y + xo.y;
                float cn = sigf(gf) * cc1 + sigf(gi) * tanh_fast(gg);
                cc1 = cn; hk1 = sigf(go) * tanh_fast(cn);
            }
        }

        // broadcast h(t+1) cell to hs2[cur^1] in ALL cluster CTAs via DSMEM
        {
            F2U u; u.f = make_float2(hk0, hk1);
            const uint32_t* rem = cur ? rem0 : rem1;
#pragma unroll
            for (int rk = 0; rk < CSIZE; rk++)
                asm volatile("st.shared::cluster.u64 [%0], %1;" :: "r"(rem[rk]), "l"(u.u) : "memory");
        }

        // prefetch xg(t+1) before the barrier (hidden under the wait)
        if (t + 1 < len_e) {
            const float* xgp = &g_xg[((size_t)(t + 1) * NBATCH + n_e) * GG + col_e];
            xi  = __ldcs((const float2*)&xgp[0]);
            xf  = __ldcs((const float2*)&xgp[256]);
            xg2 = __ldcs((const float2*)&xgp[512]);
            xo  = __ldcs((const float2*)&xgp[768]);
        }

        // hardware cluster barrier (also orders DSMEM writes; subsumes syncthreads)
        asm volatile("barrier.cluster.arrive.aligned;" ::: "memory");
        asm volatile("barrier.cluster.wait.aligned;" ::: "memory");
        cur ^= 1;
    }

    *(float2*)&out[(n_e << 8) + col_e] = make_float2(hk0, hk1);
}

// ---------------- launch ----------------
extern "C" void kernel_launch(void* const* d_in, const int* in_sizes, int n_in,
                              void* d_out, int out_size) {
    const float* attn     = (const float*)d_in[0];   // (N, T, E)
    const int*   traj_len = (const int*)d_in[1];     // (N,)
    const float* Wih      = (const float*)d_in[2];   // (4H, E)
    const float* Whh      = (const float*)d_in[3];   // (4H, H)
    const float* bih      = (const float*)d_in[4];   // (4H,)
    const float* bhh      = (const float*)d_in[5];   // (4H,)
    float* out = (float*)d_out;

    cudaFuncSetAttribute(xg_gemm_kernel, cudaFuncAttributeMaxDynamicSharedMemorySize, XG_SMEM_BYTES);
    cudaFuncSetAttribute(lstm_rec_kernel, cudaFuncAttributeMaxDynamicSharedMemorySize, 65536);

    xg_gemm_kernel<<<1024, 256, XG_SMEM_BYTES>>>(attn, Wih, bih, bhh);

    lstm_rec_kernel<<<NBLK, 256, 65536>>>(Whh, traj_len, out);

    (void)in_sizes; (void)n_in; (void)out_size;
}

// round 17
// speedup vs baseline: 1.3851x; 1.3851x over previous
#include <cuda_runtime.h>
#include <cuda_bf16.h>
#include <cstdint>
#include <cstddef>

#define TT 512
#define NBATCH 256
#define EE 256
#define HH 256
#define GG 1024
#define NBLK 128
#define GSIZE 8
#define NGROUPS 16

typedef unsigned long long ull;
union F2U { ull u; float2 f; };

// ---- packed f32x2 helpers ----
__device__ __forceinline__ ull bcast2(float x) {
    ull r; asm("mov.b64 %0, {%1, %1};" : "=l"(r) : "f"(x)); return r;
}
__device__ __forceinline__ ull pack2(float lo, float hi) {
    ull r; asm("mov.b64 %0, {%1, %2};" : "=l"(r) : "f"(lo), "f"(hi)); return r;
}
__device__ __forceinline__ void ffma2(ull& d, ull a, ull b) {
    asm("fma.rn.f32x2 %0, %1, %2, %0;" : "+l"(d) : "l"(a), "l"(b));
}

// ---- warp-MMA helpers (baseline sm_100: ldmatrix + mma.sync) ----
__device__ __forceinline__ uint32_t smem_u32(const void* p) {
    uint32_t a;
    asm("{ .reg .u64 t; cvta.to.shared.u64 t, %1; cvt.u32.u64 %0, t; }" : "=r"(a) : "l"(p));
    return a;
}
__device__ __forceinline__ void ldsm_x4(uint32_t* r, uint32_t addr) {
    asm volatile("ldmatrix.sync.aligned.m8n8.x4.shared.b16 {%0,%1,%2,%3}, [%4];"
                 : "=r"(r[0]), "=r"(r[1]), "=r"(r[2]), "=r"(r[3]) : "r"(addr));
}
__device__ __forceinline__ void ldsm_x2(uint32_t* r, uint32_t addr) {
    asm volatile("ldmatrix.sync.aligned.m8n8.x2.shared.b16 {%0,%1}, [%2];"
                 : "=r"(r[0]), "=r"(r[1]) : "r"(addr));
}
__device__ __forceinline__ void mma16816(float* d, const uint32_t* a, const uint32_t* b) {
    asm volatile(
        "mma.sync.aligned.m16n8k16.row.col.f32.bf16.bf16.f32 "
        "{%0,%1,%2,%3}, {%4,%5,%6,%7}, {%8,%9}, {%0,%1,%2,%3};"
        : "+f"(d[0]), "+f"(d[1]), "+f"(d[2]), "+f"(d[3])
        : "r"(a[0]), "r"(a[1]), "r"(a[2]), "r"(a[3]), "r"(b[0]), "r"(b[1]));
}
__device__ __forceinline__ uint32_t sw128(uint32_t bo) { return bo ^ ((bo >> 3) & 0x70); }

// ---------------- device scratch ----------------
__device__ __align__(16) float g_xg[(size_t)TT * NBATCH * GG];
__device__ __align__(16) float g_hbuf[2][NBATCH * HH];
__device__ __align__(128) unsigned int g_gbar[NGROUPS * 32];

__device__ __forceinline__ void split_store(char* hi_p, char* lo_p, float4 v) {
    __nv_bfloat16 hx = __float2bfloat16(v.x), hy = __float2bfloat16(v.y),
                  hz = __float2bfloat16(v.z), hw = __float2bfloat16(v.w);
    __nv_bfloat16 lx = __float2bfloat16(v.x - __bfloat162float(hx));
    __nv_bfloat16 ly = __float2bfloat16(v.y - __bfloat162float(hy));
    __nv_bfloat16 lz = __float2bfloat16(v.z - __bfloat162float(hz));
    __nv_bfloat16 lw = __float2bfloat16(v.w - __bfloat162float(hw));
    union { __nv_bfloat162 b[2]; uint2 u; } H, L;
    H.b[0] = __halves2bfloat162(hx, hy); H.b[1] = __halves2bfloat162(hz, hw);
    L.b[0] = __halves2bfloat162(lx, ly); L.b[1] = __halves2bfloat162(lz, lw);
    *(uint2*)hi_p = H.u;
    *(uint2*)lo_p = L.u;
}

// ---------------- phase 1: xg = x @ Wih^T + biases (split-bf16 mma.sync) ----------------
// validated R14 design, fused graph-replay reset retained
__global__ void __launch_bounds__(256, 1) xg_gemm_kernel(
    const float* __restrict__ attn,   // (N, T, E)
    const float* __restrict__ Wih,    // (4H, E)
    const float* __restrict__ bih,
    const float* __restrict__ bhh) {
    extern __shared__ char dsm[];
    __shared__ float sbias[1024];

    const int mt = blockIdx.x;                 // 0..1023
    const int t  = mt >> 1;
    const int n0 = (mt & 1) << 7;
    const int tid = threadIdx.x;
    const int wid = tid >> 5, lane = tid & 31;

    // fused graph-replay-safe reset
    if (mt < 64) {
        int i = (mt << 8) + tid;
        *(float4*)&g_hbuf[0][i << 2] = make_float4(0.f, 0.f, 0.f, 0.f);
    } else if (mt == 64) {
        g_gbar[tid] = 0u;
        g_gbar[tid + 256] = 0u;
    }

    const uint32_t dsm_u = smem_u32(dsm);
    const uint32_t base_u = (dsm_u + 1023u) & ~1023u;
    char* p = dsm + (base_u - dsm_u);
    char* aHi = p;
    char* aLo = p + 65536;
    char* bBuf = p + 131072;
    const uint32_t uaHi = base_u, uaLo = base_u + 65536, ubBuf = base_u + 131072;

    for (int i = tid; i < 1024; i += 256) sbias[i] = bih[i] + bhh[i];

    {
        const int arow = tid >> 4;
        const int acol = tid & 15;
#pragma unroll 1
        for (int round = 0; round < 8; round++) {
            int row = (round << 4) + arow;
            const float4* src = (const float4*)(attn + ((size_t)(n0 + row) * TT + t) * EE);
#pragma unroll
            for (int q = 0; q < 4; q++) {
                int c4 = acol + (q << 4);
                float4 v = src[c4];
                int kch = c4 >> 4;
                uint32_t so = sw128((row << 7) + ((c4 & 15) << 3));
                split_store(aHi + kch * 16384 + so, aLo + kch * 16384 + so, v);
            }
        }
    }

    const int brow_l = tid >> 4;
    const int bcol_l = tid & 15;

    float4 vb[8];
    {
        const float* wbase = Wih;
#pragma unroll
        for (int r = 0; r < 8; r++) {
            int row = (r << 4) + brow_l;
            vb[r] = *(const float4*)(wbase + (size_t)row * EE + (bcol_l << 2));
        }
#pragma unroll
        for (int r = 0; r < 8; r++) {
            int row = (r << 4) + brow_l;
            uint32_t so = sw128((row << 7) + (bcol_l << 3));
            split_store(bBuf + so, bBuf + 16384 + so, vb[r]);
        }
    }
    __syncthreads();

    const int m_base = (wid & 1) << 6;
    const int nb     = (wid >> 1) << 5;
    const int a_r = lane & 15;
    const int a_c = (lane >> 4) << 3;
    const int b_r = lane & 7;
    const int b_c = ((lane >> 3) & 1) << 3;
    const int gID = lane >> 2, t4 = lane & 3;

    int buf = 0;

#pragma unroll 1
    for (int gt = 0; gt < 8; gt++) {
        float d[4][4][4];
#pragma unroll
        for (int mi = 0; mi < 4; mi++)
#pragma unroll
            for (int ni = 0; ni < 4; ni++)
#pragma unroll
                for (int q = 0; q < 4; q++) d[mi][ni][q] = 0.f;

#pragma unroll 1
        for (int kch = 0; kch < 4; kch++) {
            const bool have_next = !(gt == 7 && kch == 3);
            if (have_next) {
                const int ngt = gt + (kch == 3 ? 1 : 0);
                const int nkch = (kch + 1) & 3;
                const float* wbase = Wih + (size_t)(ngt << 7) * EE + (nkch << 6);
#pragma unroll
                for (int r = 0; r < 8; r++) {
                    int row = (r << 4) + brow_l;
                    vb[r] = *(const float4*)(wbase + (size_t)row * EE + (bcol_l << 2));
                }
            }

            const uint32_t aH = uaHi + kch * 16384;
            const uint32_t aL = uaLo + kch * 16384;
            const uint32_t bH = ubBuf + buf * 32768;
            const uint32_t bL = bH + 16384;
#pragma unroll
            for (int combo = 0; combo < 3; combo++) {
                const uint32_t aBase = (combo == 2) ? aL : aH;
                const uint32_t bBase = (combo == 1) ? bL : bH;
#pragma unroll
                for (int k16 = 0; k16 < 4; k16++) {
                    const int kc = k16 << 4;
                    uint32_t afr[4][4];
#pragma unroll
                    for (int mi = 0; mi < 4; mi++) {
                        uint32_t bo = ((m_base + (mi << 4) + a_r) << 7) + ((kc + a_c) << 1);
                        ldsm_x4(afr[mi], aBase + sw128(bo));
                    }
                    uint32_t bfr[4][2];
#pragma unroll
                    for (int ni = 0; ni < 4; ni++) {
                        uint32_t bo = ((nb + (ni << 3) + b_r) << 7) + ((kc + b_c) << 1);
                        ldsm_x2(bfr[ni], bBase + sw128(bo));
                    }
#pragma unroll
                    for (int mi = 0; mi < 4; mi++)
#pragma unroll
                        for (int ni = 0; ni < 4; ni++)
                            mma16816(d[mi][ni], afr[mi], bfr[ni]);
                }
            }

            if (have_next) {
                char* nh = bBuf + (buf ^ 1) * 32768;
                char* nl = nh + 16384;
#pragma unroll
                for (int r = 0; r < 8; r++) {
                    int row = (r << 4) + brow_l;
                    uint32_t so = sw128((row << 7) + (bcol_l << 3));
                    split_store(nh + so, nl + so, vb[r]);
                }
            }
            __syncthreads();
            buf ^= 1;
        }

        const int g0 = gt << 7;
#pragma unroll
        for (int mi = 0; mi < 4; mi++) {
            const int row0 = m_base + (mi << 4) + gID;
#pragma unroll
            for (int ni = 0; ni < 4; ni++) {
                const int col = nb + (ni << 3) + (t4 << 1);
                const float bx = sbias[g0 + col], by = sbias[g0 + col + 1];
                size_t base0 = ((size_t)t * NBATCH + (n0 + row0)) * GG + g0 + col;
                size_t base1 = base0 + (size_t)8 * GG;
                *(float2*)&g_xg[base0] = make_float2(d[mi][ni][0] + bx, d[mi][ni][1] + by);
                *(float2*)&g_xg[base1] = make_float2(d[mi][ni][2] + bx, d[mi][ni][3] + by);
            }
        }
    }
}

#define XG_SMEM_BYTES (196608 + 1024)

// ---------------- phase 2: persistent recurrent kernel ----------------
__device__ __forceinline__ float sigf(float x) { return 1.0f / (1.0f + __expf(-x)); }
__device__ __forceinline__ float tanh_fast(float x) { return 1.0f - 2.0f / (__expf(2.0f * x) + 1.0f); }

// 128 CTAs, 16 groups of 8 (L2 ticket barrier per group — the R14 design).
// NEW: warp-local h staging (each warp stages only its own K-slice, __syncwarp
// instead of a CTA barrier; absorbs per-warp load skew), and frozen rows stop
// publishing after t > len (consumers skip them anyway; both buffers hold h(len)).
__global__ void __launch_bounds__(256, 1) lstm_rec_kernel(
    const float* __restrict__ Whh,       // (4H, H)
    const int*   __restrict__ traj_len,  // (N,)
    float*       __restrict__ out) {     // (N, 1, H)
    extern __shared__ float red[];       // 64 KB dynamic
    __shared__ float hs[16 * 256];       // 16 KB h tile (warp-sliced)
    __shared__ int slen[16];

    const int tid = threadIdx.x;
    const int bid = blockIdx.x;
    const int bn = bid & 15, bj = bid >> 4;
    const int r0 = bn << 4;
    const int c0 = bj << 5;
    const int ks = tid >> 5, gcg = tid & 31;

    // pack W_hh slice into f32x2 gate-pair registers
    ull pwA[32], pwB[32];
    {
        const float* wr[4];
#pragma unroll
        for (int q = 0; q < 4; q++) {
            int l = (gcg << 2) + q;
            int gr = ((l >> 5) << 8) + c0 + (l & 31);
            wr[q] = &Whh[(size_t)gr * HH + (ks << 5)];
        }
#pragma unroll
        for (int kc = 0; kc < 8; kc++) {
            float4 w0 = *(const float4*)(wr[0] + (kc << 2));
            float4 w1 = *(const float4*)(wr[1] + (kc << 2));
            float4 w2 = *(const float4*)(wr[2] + (kc << 2));
            float4 w3 = *(const float4*)(wr[3] + (kc << 2));
            pwA[(kc << 2) + 0] = pack2(w0.x, w1.x);
            pwA[(kc << 2) + 1] = pack2(w0.y, w1.y);
            pwA[(kc << 2) + 2] = pack2(w0.z, w1.z);
            pwA[(kc << 2) + 3] = pack2(w0.w, w1.w);
            pwB[(kc << 2) + 0] = pack2(w2.x, w3.x);
            pwB[(kc << 2) + 1] = pack2(w2.y, w3.y);
            pwB[(kc << 2) + 2] = pack2(w2.z, w3.z);
            pwB[(kc << 2) + 3] = pack2(w2.w, w3.w);
        }
    }

    if (tid < 16) slen[tid] = traj_len[r0 + tid];

    const int er = tid >> 4, ep = tid & 15;
    const int n_e = r0 + er;
    const int len_e = traj_len[n_e];
    const int col_e = c0 + (ep << 1);
    float cc0 = 0.f, cc1 = 0.f, hk0 = 0.f, hk1 = 0.f;

    // warp-local staging indices: instr q covers rows 4q..4q+3
    const int srow = gcg >> 3;                 // 0..3 row-within-quad
    const int sc4  = gcg & 7;                  // float4 col 0..7

    unsigned int* barp = &g_gbar[bn << 5];
    __syncthreads();

    int gmax = 0;
#pragma unroll
    for (int r = 0; r < 16; r++) gmax = max(gmax, slen[r]);

    for (int t = 0; t < gmax; t++) {
        const bool valid = (t < len_e);

        // prefetch xg(t) before the spin (recurrence-independent)
        float2 xi, xf, xg2, xo;
        if (valid) {
            const float* xgp = &g_xg[((size_t)t * NBATCH + n_e) * GG + col_e];
            xi  = __ldcs((const float2*)&xgp[0]);
            xf  = __ldcs((const float2*)&xgp[256]);
            xg2 = __ldcs((const float2*)&xgp[512]);
            xo  = __ldcs((const float2*)&xgp[768]);
        }

        if (t > 0) {
            if (tid == 0) {
                const unsigned target = (unsigned)t * GSIZE;
                unsigned v;
                do {
                    asm volatile("ld.acquire.gpu.global.u32 %0, [%1];"
                                 : "=r"(v) : "l"(barp) : "memory");
                } while (v < target);
            }
            __syncthreads();
        }

        // warp-local staging: warp ks stages ONLY its K-slice of the 16-row tile
        {
            const float* srcbase = &g_hbuf[t & 1][(r0 << 8) + (ks << 5)];
#pragma unroll
            for (int q = 0; q < 4; q++) {
                int row = (q << 2) + srow;
                float4 v = __ldcg((const float4*)(srcbase + (row << 8)) + sc4);
                *(float4*)&hs[(row << 8) + (ks << 5) + (sc4 << 2)] = v;
            }
            __syncwarp();
        }

        // GEMM partials over this warp's K-slice — skip frozen rows (uniform branch)
#pragma unroll 2
        for (int r = 0; r < 16; r++) {
            if (t < slen[r]) {
                const float4* hp = (const float4*)&hs[(r << 8) + (ks << 5)];
                ull accA = 0ull, accB = 0ull;
#pragma unroll
                for (int kc = 0; kc < 8; kc++) {
                    float4 hv = hp[kc];
                    ull h0 = bcast2(hv.x), h1 = bcast2(hv.y), h2 = bcast2(hv.z), h3 = bcast2(hv.w);
                    ffma2(accA, h0, pwA[(kc << 2) + 0]); ffma2(accB, h0, pwB[(kc << 2) + 0]);
                    ffma2(accA, h1, pwA[(kc << 2) + 1]); ffma2(accB, h1, pwB[(kc << 2) + 1]);
                    ffma2(accA, h2, pwA[(kc << 2) + 2]); ffma2(accB, h2, pwB[(kc << 2) + 2]);
                    ffma2(accA, h3, pwA[(kc << 2) + 3]); ffma2(accB, h3, pwB[(kc << 2) + 3]);
                }
                ulonglong2 st; st.x = accA; st.y = accB;
                *(ulonglong2*)&red[(((ks << 4) + r) << 7) + (gcg << 2)] = st;
            }
        }
        __syncthreads();

        if (valid) {
            float2 s[4];
#pragma unroll
            for (int typ = 0; typ < 4; typ++) {
                float sx = 0.f, sy = 0.f;
#pragma unroll
                for (int k2 = 0; k2 < 8; k2++) {
                    float2 v = *(const float2*)&red[(k2 << 11) + (er << 7) + (typ << 5) + (ep << 1)];
                    sx += v.x; sy += v.y;
                }
                s[typ] = make_float2(sx, sy);
            }
            {
                float gi = s[0].x + xi.x, gf = s[1].x + xf.x, gg = s[2].x + xg2.x, go = s[3].x + xo.x;
                float cn = sigf(gf) * cc0 + sigf(gi) * tanh_fast(gg);
                cc0 = cn; hk0 = sigf(go) * tanh_fast(cn);
            }
            {
                float gi = s[0].y + xi.y, gf = s[1].y + xf.y, gg = s[2].y + xg2.y, go = s[3].y + xo.y;
                float cn = sigf(gf) * cc1 + sigf(gi) * tanh_fast(gg);
                cc1 = cn; hk1 = sigf(go) * tanh_fast(cn);
            }
        }

        // publish h(t+1); frozen rows stop after t == len (both buffers then hold h(len))
        if (t <= len_e)
            *(float2*)&g_hbuf[(t + 1) & 1][(n_e << 8) + col_e] = make_float2(hk0, hk1);

        __syncthreads();
        if (tid == 0 && t + 1 < gmax) {
            asm volatile("red.release.gpu.global.add.u32 [%0], %1;"
                         :: "l"(barp), "r"(1u) : "memory");
        }
    }

    *(float2*)&out[(n_e << 8) + col_e] = make_float2(hk0, hk1);
}

// ---------------- launch ----------------
extern "C" void kernel_launch(void* const* d_in, const int* in_sizes, int n_in,
                              void* d_out, int out_size) {
    const float* attn     = (const float*)d_in[0];
    const int*   traj_len = (const int*)d_in[1];
    const float* Wih      = (const float*)d_in[2];
    const float* Whh      = (const float*)d_in[3];
    const float* bih      = (const float*)d_in[4];
    const float* bhh      = (const float*)d_in[5];
    float* out = (float*)d_out;

    cudaFuncSetAttribute(xg_gemm_kernel, cudaFuncAttributeMaxDynamicSharedMemorySize, XG_SMEM_BYTES);
    cudaFuncSetAttribute(lstm_rec_kernel, cudaFuncAttributeMaxDynamicSharedMemorySize, 65536);

    xg_gemm_kernel<<<1024, 256, XG_SMEM_BYTES>>>(attn, Wih, bih, bhh);

    lstm_rec_kernel<<<NBLK, 256, 65536>>>(Whh, traj_len, out);

    (void)in_sizes; (void)n_in; (void)out_size;
}